// round 1
// baseline (speedup 1.0000x reference)
#include <cuda_runtime.h>
#include <cstdint>

#define NN 50000
#define NE 800000

// ---------------- scratch (device globals; no allocation allowed) ----------------
__device__ __align__(16) float g_agg[NN * 96];
__device__ __align__(16) float g_h  [NN * 96];
__device__ __align__(16) float g_x1 [NN * 96];
__device__ __align__(16) float g_x2 [NN * 64];
__device__ __align__(16) float g_x3 [NN * 96];
__device__ __align__(16) float g_x4 [NN * 96];
__device__ __align__(16) float g_sum[96];
__device__ __align__(16) float g_sq [96];
__device__ __align__(16) float g_scale[96];
__device__ __align__(16) float g_shift[96];

// ---------------- edge message + scatter-add ----------------
// msg = relu(x[src] + (ea*lin_w + lin_b)); agg[dst] += msg
// one thread per (edge, float4-chunk); 24 chunks of 4 floats = 96 cols
__global__ void edge_kernel(const float* __restrict__ x,
                            const float* __restrict__ ea,
                            const int*   __restrict__ src,
                            const int*   __restrict__ dst,
                            const float* __restrict__ lw,
                            const float* __restrict__ lb,
                            float* __restrict__ agg)
{
    long long tid = (long long)blockIdx.x * blockDim.x + threadIdx.x;
    if (tid >= (long long)NE * 24) return;
    int i = (int)(tid / 24);
    int c = (int)(tid - (long long)i * 24);

    int   s = src[i];
    int   d = dst[i];
    float a = ea[i];

    float4 lw4 = reinterpret_cast<const float4*>(lw)[c];
    float4 lb4 = reinterpret_cast<const float4*>(lb)[c];
    float4 xv  = reinterpret_cast<const float4*>(x + (size_t)s * 96)[c];

    float4 m;
    m.x = fmaxf(fmaf(a, lw4.x, lb4.x) + xv.x, 0.0f);
    m.y = fmaxf(fmaf(a, lw4.y, lb4.y) + xv.y, 0.0f);
    m.z = fmaxf(fmaf(a, lw4.z, lb4.z) + xv.z, 0.0f);
    m.w = fmaxf(fmaf(a, lw4.w, lb4.w) + xv.w, 0.0f);

    float* p = agg + (size_t)d * 96 + c * 4;
    asm volatile("red.global.add.v4.f32 [%0], {%1, %2, %3, %4};"
                 :: "l"(p), "f"(m.x), "f"(m.y), "f"(m.z), "f"(m.w)
                 : "memory");
}

// ---------------- fused GEMM + bias + ReLU + BN stats ----------------
// H[M,BN] = relu( (A (+Aadd) | concat B2)[M,K] @ W[K,BN] + bias ), accumulate
// per-column sum / sumsq into gsum/gsumsq.
// A has leading dim K1; when B2 != nullptr, cols >= K1 come from B2 (ld = K-K1).
template<int BN, int TX, int TY, int TM>
__global__ void gemm_kernel(const float* __restrict__ A,
                            const float* __restrict__ Aadd,
                            const float* __restrict__ B2,
                            int K, int K1,
                            const float* __restrict__ W,
                            const float* __restrict__ bias,
                            float* __restrict__ H,
                            float* __restrict__ gsum,
                            float* __restrict__ gsumsq,
                            int M)
{
    constexpr int BK = 32;
    constexpr int BM = TY * TM;           // 64 in all configs
    constexpr int THREADS = TX * TY;
    constexpr int S = BM + 4;             // padded, keeps rows 16B-aligned

    __shared__ float At[BK][S];           // transposed A tile: At[k][m]
    __shared__ float Wt[BK][BN];
    __shared__ float s_sum[BN];
    __shared__ float s_sq [BN];

    const int tid = threadIdx.x;
    const int tx  = tid % TX;
    const int ty  = tid / TX;
    const int m0  = blockIdx.x * BM;
    const int K2  = K - K1;

    for (int t = tid; t < BN; t += THREADS) { s_sum[t] = 0.f; s_sq[t] = 0.f; }

    float acc[TM][4];
#pragma unroll
    for (int i = 0; i < TM; i++) { acc[i][0]=0.f; acc[i][1]=0.f; acc[i][2]=0.f; acc[i][3]=0.f; }

    for (int kb = 0; kb < K; kb += BK) {
        // load A tile (transposed). Each thread: one float4 along k, 4 scalar STS.
        for (int t = tid; t < BM * (BK / 4); t += THREADS) {
            int m  = t >> 3;            // BK/4 == 8
            int k4 = (t & 7) * 4;
            int row = m0 + m;
            float4 v = make_float4(0.f, 0.f, 0.f, 0.f);
            if (row < M) {
                int gc = kb + k4;
                if (B2 != nullptr && gc >= K1) {
                    v = *reinterpret_cast<const float4*>(B2 + (size_t)row * K2 + (gc - K1));
                } else {
                    v = *reinterpret_cast<const float4*>(A + (size_t)row * K1 + gc);
                    if (Aadd != nullptr) {
                        float4 v2 = *reinterpret_cast<const float4*>(Aadd + (size_t)row * K1 + gc);
                        v.x += v2.x; v.y += v2.y; v.z += v2.z; v.w += v2.w;
                    }
                }
            }
            At[k4 + 0][m] = v.x;
            At[k4 + 1][m] = v.y;
            At[k4 + 2][m] = v.z;
            At[k4 + 3][m] = v.w;
        }
        // load W tile (row-major copy, coalesced)
        for (int t = tid; t < BK * (BN / 4); t += THREADS) {
            int k  = t / (BN / 4);
            int c4 = (t % (BN / 4)) * 4;
            float4 v = *reinterpret_cast<const float4*>(W + (size_t)(kb + k) * BN + c4);
            *reinterpret_cast<float4*>(&Wt[k][c4]) = v;
        }
        __syncthreads();

#pragma unroll 8
        for (int k = 0; k < BK; k++) {
            float4 wv = *reinterpret_cast<const float4*>(&Wt[k][tx * 4]);
            float av[TM];
            if constexpr (TM % 4 == 0) {
#pragma unroll
                for (int ii = 0; ii < TM / 4; ii++) {
                    float4 a4 = *reinterpret_cast<const float4*>(&At[k][ty * TM + ii * 4]);
                    av[ii*4+0] = a4.x; av[ii*4+1] = a4.y; av[ii*4+2] = a4.z; av[ii*4+3] = a4.w;
                }
            } else {
                float2 a2 = *reinterpret_cast<const float2*>(&At[k][ty * TM]);
                av[0] = a2.x; av[1] = a2.y;
            }
#pragma unroll
            for (int i = 0; i < TM; i++) {
                acc[i][0] = fmaf(av[i], wv.x, acc[i][0]);
                acc[i][1] = fmaf(av[i], wv.y, acc[i][1]);
                acc[i][2] = fmaf(av[i], wv.z, acc[i][2]);
                acc[i][3] = fmaf(av[i], wv.w, acc[i][3]);
            }
        }
        __syncthreads();
    }

    // epilogue: bias + relu + store + BN stats
    float4 b4 = *reinterpret_cast<const float4*>(bias + tx * 4);
    float csum[4] = {0.f, 0.f, 0.f, 0.f};
    float csq [4] = {0.f, 0.f, 0.f, 0.f};
#pragma unroll
    for (int i = 0; i < TM; i++) {
        int row = m0 + ty * TM + i;
        if (row < M) {
            float4 o;
            o.x = fmaxf(acc[i][0] + b4.x, 0.f);
            o.y = fmaxf(acc[i][1] + b4.y, 0.f);
            o.z = fmaxf(acc[i][2] + b4.z, 0.f);
            o.w = fmaxf(acc[i][3] + b4.w, 0.f);
            *reinterpret_cast<float4*>(H + (size_t)row * BN + tx * 4) = o;
            csum[0] += o.x; csum[1] += o.y; csum[2] += o.z; csum[3] += o.w;
            csq [0] += o.x * o.x; csq[1] += o.y * o.y; csq[2] += o.z * o.z; csq[3] += o.w * o.w;
        }
    }
    atomicAdd(&s_sum[tx * 4 + 0], csum[0]);
    atomicAdd(&s_sum[tx * 4 + 1], csum[1]);
    atomicAdd(&s_sum[tx * 4 + 2], csum[2]);
    atomicAdd(&s_sum[tx * 4 + 3], csum[3]);
    atomicAdd(&s_sq [tx * 4 + 0], csq[0]);
    atomicAdd(&s_sq [tx * 4 + 1], csq[1]);
    atomicAdd(&s_sq [tx * 4 + 2], csq[2]);
    atomicAdd(&s_sq [tx * 4 + 3], csq[3]);
    __syncthreads();
    for (int t = tid; t < BN; t += THREADS) {
        atomicAdd(gsum   + t, s_sum[t]);
        atomicAdd(gsumsq + t, s_sq[t]);
    }
}

// ---------------- BN finalize: scale/shift per column ----------------
__global__ void finalize_kernel(const float* __restrict__ gsum,
                                const float* __restrict__ gsumsq,
                                const float* __restrict__ g,
                                const float* __restrict__ beta,
                                float* __restrict__ scale,
                                float* __restrict__ shift,
                                int BNc, int M)
{
    int t = threadIdx.x;
    if (t < BNc) {
        float invM = 1.0f / (float)M;
        float mu   = gsum[t] * invM;
        float var  = gsumsq[t] * invM - mu * mu;
        float inv  = rsqrtf(var + 1e-5f);
        float sc   = g[t] * inv;
        scale[t] = sc;
        shift[t] = fmaf(-mu, sc, beta[t]);
    }
}

// ---------------- apply BN affine ----------------
__global__ void norm_kernel(const float* __restrict__ Hin,
                            const float* __restrict__ scale,
                            const float* __restrict__ shift,
                            float* __restrict__ out,
                            int n4, int cols4)
{
    int i = blockIdx.x * blockDim.x + threadIdx.x;
    if (i >= n4) return;
    int c4 = (i % cols4) * 4;
    float4 v  = reinterpret_cast<const float4*>(Hin)[i];
    float4 sc = *reinterpret_cast<const float4*>(scale + c4);
    float4 sh = *reinterpret_cast<const float4*>(shift + c4);
    float4 r;
    r.x = fmaf(v.x, sc.x, sh.x);
    r.y = fmaf(v.y, sc.y, sh.y);
    r.z = fmaf(v.z, sc.z, sh.z);
    r.w = fmaf(v.w, sc.w, sh.w);
    reinterpret_cast<float4*>(out)[i] = r;
}

// ---------------- host orchestration ----------------
extern "C" void kernel_launch(void* const* d_in, const int* in_sizes, int n_in,
                              void* d_out, int out_size)
{
    const float* x   = (const float*)d_in[0];
    const float* ea  = (const float*)d_in[1];
    const int*   ei  = (const int*)  d_in[2];
    const float* lw  = (const float*)d_in[3];
    const float* lb  = (const float*)d_in[4];
    const float* w1  = (const float*)d_in[5];
    const float* b1  = (const float*)d_in[6];
    const float* g1  = (const float*)d_in[7];
    const float* be1 = (const float*)d_in[8];
    const float* w2  = (const float*)d_in[9];
    const float* b2  = (const float*)d_in[10];
    const float* g2  = (const float*)d_in[11];
    const float* be2 = (const float*)d_in[12];
    const float* w3  = (const float*)d_in[13];
    const float* b3  = (const float*)d_in[14];
    const float* g3  = (const float*)d_in[15];
    const float* be3 = (const float*)d_in[16];
    const float* w4  = (const float*)d_in[17];
    const float* b4  = (const float*)d_in[18];
    const float* g4  = (const float*)d_in[19];
    const float* be4 = (const float*)d_in[20];
    const float* w5  = (const float*)d_in[21];
    const float* b5  = (const float*)d_in[22];
    const float* g5  = (const float*)d_in[23];
    const float* be5 = (const float*)d_in[24];
    float* out = (float*)d_out;

    const int* srcp = ei;
    const int* dstp = ei + NE;

    float *agg, *h, *x1, *x2, *x3, *x4, *sum, *sq, *scale, *shift;
    cudaGetSymbolAddress((void**)&agg,   g_agg);
    cudaGetSymbolAddress((void**)&h,     g_h);
    cudaGetSymbolAddress((void**)&x1,    g_x1);
    cudaGetSymbolAddress((void**)&x2,    g_x2);
    cudaGetSymbolAddress((void**)&x3,    g_x3);
    cudaGetSymbolAddress((void**)&x4,    g_x4);
    cudaGetSymbolAddress((void**)&sum,   g_sum);
    cudaGetSymbolAddress((void**)&sq,    g_sq);
    cudaGetSymbolAddress((void**)&scale, g_scale);
    cudaGetSymbolAddress((void**)&shift, g_shift);

    const int M = NN;
    const int gblocks = (M + 63) / 64;
    const long long etotal = (long long)NE * 24;
    const int eblocks = (int)((etotal + 255) / 256);

    // ---- conv1 ----
    cudaMemsetAsync(agg, 0, sizeof(float) * NN * 96, 0);
    edge_kernel<<<eblocks, 256>>>(x, ea, srcp, dstp, lw, lb, agg);
    cudaMemsetAsync(sum, 0, 96 * sizeof(float), 0);
    cudaMemsetAsync(sq,  0, 96 * sizeof(float), 0);
    gemm_kernel<96, 24, 8, 8><<<gblocks, 192>>>(x, agg, nullptr, 96, 96, w1, b1, h, sum, sq, M);
    finalize_kernel<<<1, 96>>>(sum, sq, g1, be1, scale, shift, 96, M);
    norm_kernel<<<(M * 24 + 255) / 256, 256>>>(h, scale, shift, x1, M * 24, 24);

    // ---- conv2 ----
    cudaMemsetAsync(agg, 0, sizeof(float) * NN * 96, 0);
    edge_kernel<<<eblocks, 256>>>(x1, ea, srcp, dstp, lw, lb, agg);
    cudaMemsetAsync(sum, 0, 96 * sizeof(float), 0);
    cudaMemsetAsync(sq,  0, 96 * sizeof(float), 0);
    gemm_kernel<64, 16, 16, 4><<<gblocks, 256>>>(x1, agg, nullptr, 96, 96, w2, b2, h, sum, sq, M);
    finalize_kernel<<<1, 64>>>(sum, sq, g2, be2, scale, shift, 64, M);
    norm_kernel<<<(M * 16 + 255) / 256, 256>>>(h, scale, shift, x2, M * 16, 16);

    // ---- lin1: concat(x1, x2) @ w3 ----
    cudaMemsetAsync(sum, 0, 96 * sizeof(float), 0);
    cudaMemsetAsync(sq,  0, 96 * sizeof(float), 0);
    gemm_kernel<96, 24, 8, 8><<<gblocks, 192>>>(x1, nullptr, x2, 160, 96, w3, b3, h, sum, sq, M);
    finalize_kernel<<<1, 96>>>(sum, sq, g3, be3, scale, shift, 96, M);
    norm_kernel<<<(M * 24 + 255) / 256, 256>>>(h, scale, shift, x3, M * 24, 24);

    // ---- mlp1a ----
    cudaMemsetAsync(sum, 0, 96 * sizeof(float), 0);
    cudaMemsetAsync(sq,  0, 96 * sizeof(float), 0);
    gemm_kernel<96, 24, 8, 8><<<gblocks, 192>>>(x3, nullptr, nullptr, 96, 96, w4, b4, h, sum, sq, M);
    finalize_kernel<<<1, 96>>>(sum, sq, g4, be4, scale, shift, 96, M);
    norm_kernel<<<(M * 24 + 255) / 256, 256>>>(h, scale, shift, x4, M * 24, 24);

    // ---- mlp1b -> output ----
    cudaMemsetAsync(sum, 0, 96 * sizeof(float), 0);
    cudaMemsetAsync(sq,  0, 96 * sizeof(float), 0);
    gemm_kernel<16, 4, 32, 2><<<gblocks, 128>>>(x4, nullptr, nullptr, 96, 96, w5, b5, h, sum, sq, M);
    finalize_kernel<<<1, 16>>>(sum, sq, g5, be5, scale, shift, 16, M);
    norm_kernel<<<(M * 4 + 255) / 256, 256>>>(h, scale, shift, out, M * 4, 4);

    (void)in_sizes; (void)n_in; (void)out_size;
}